// round 6
// baseline (speedup 1.0000x reference)
#include <cuda_runtime.h>

// Problem constants (LatentCoulombLongRange: N=8192, F=128, H=64, B=8)
#define MAXN 8192
#define FDIM 128
#define HDIM 64
#define MAXB 64
#define NSLOT 32          // charge-sum slots per graph (atomic de-serialization)
#define ATOMS_PER_BLK 16  // MLP: atoms per 256-thread block (2 per warp)

// Scratch (allocation-free rule: __device__ globals; zero-initialized at load)
__device__ float  d_qraw[MAXN];
__device__ float4 d_qpos[MAXN];            // {x, y, z, centered q}
__device__ int    d_gstart[MAXB];
__device__ int    d_gend[MAXB];
__device__ float  d_gsum[MAXB * NSLOT];    // slotted per-graph q sums; re-zeroed by pair_kernel

// ---- raw single-MUFU intrinsics (avoid non-fast-math slow paths) ----------
__device__ __forceinline__ float fast_rsqrt(float x) {
    float r; asm("rsqrt.approx.ftz.f32 %0, %1;" : "=f"(r) : "f"(x)); return r;
}
__device__ __forceinline__ float fast_ex2(float x) {
    float r; asm("ex2.approx.ftz.f32 %0, %1;" : "=f"(r) : "f"(x)); return r;
}
__device__ __forceinline__ float fast_rcp(float x) {
    float r; asm("rcp.approx.ftz.f32 %0, %1;" : "=f"(r) : "f"(x)); return r;
}

#define LOG2E 1.44269504088896f

// ---------------------------------------------------------------------------
// K1: charge-head MLP  q_raw[i] = (silu(x W1 + b1) W2 + b2)
//     Block = 256 threads / 8 warps, 16 atoms per block (2 per warp).
//     W1 (32KB) and the block's x rows (8KB) are staged in SMEM, so the
//     inner loop is pure LDS + FFMA: 1 LDS.64 (w) + 2 LDS bcast (x) + 4 FFMA
//     per f-step. Grid = 512 blocks -> 4096 warps (occ ~43%) to hide LDS lat.
// ---------------------------------------------------------------------------
__global__ void mlp_kernel(const float* __restrict__ x,
                           const float* __restrict__ W1,
                           const float* __restrict__ b1,
                           const float* __restrict__ W2,
                           const float* __restrict__ b2,
                           const int* __restrict__ batch,
                           int n) {
    int warp = threadIdx.x >> 5;           // 0..7
    int lane = threadIdx.x & 31;
    int base = blockIdx.x * ATOMS_PER_BLK;

    __shared__ float sw[FDIM * HDIM];          // 32 KB, row f: 64 floats
    __shared__ float sx[ATOMS_PER_BLK][FDIM];  // 8 KB

    // stage W1: 8192 floats = 2048 float4, 256 threads x 8
    {
        const float4* wv = (const float4*)W1;
        float4*       dv = (float4*)sw;
#pragma unroll
        for (int t = 0; t < 8; t++)
            dv[threadIdx.x + t * 256] = wv[threadIdx.x + t * 256];
    }
    // stage x rows: 16 rows x 32 float4 = 512 float4, 256 threads x 2
    {
        const float4* xv = (const float4*)(x + (size_t)base * FDIM);
#pragma unroll
        for (int t = 0; t < 2; t++) {
            int idx = threadIdx.x + t * 256;   // 0..511
            ((float4*)sx[idx >> 5])[idx & 31] = xv[idx];
        }
    }
    __syncthreads();

    int a0 = warp * 2;                     // local atoms a0, a0+1
    const float2* swv = (const float2*)sw; // [128][32] float2
    float2 bb = ((const float2*)b1)[lane];
    float2 acc0 = bb, acc1 = bb;

#pragma unroll
    for (int f = 0; f < FDIM; f++) {
        float2 w = swv[f * 32 + lane];
        float x0 = sx[a0 + 0][f];
        float x1 = sx[a0 + 1][f];
        acc0.x = fmaf(x0, w.x, acc0.x);  acc0.y = fmaf(x0, w.y, acc0.y);
        acc1.x = fmaf(x1, w.x, acc1.x);  acc1.y = fmaf(x1, w.y, acc1.y);
    }

    // SiLU + W2 contraction, then 2 warp reductions
    float2 w2 = ((const float2*)W2)[lane];
    float q[2];
#pragma unroll
    for (int a = 0; a < 2; a++) {
        float2 acc = (a == 0) ? acc0 : acc1;
        float s0 = acc.x * fast_rcp(1.0f + fast_ex2(-LOG2E * acc.x));
        float s1 = acc.y * fast_rcp(1.0f + fast_ex2(-LOG2E * acc.y));
        float v = fmaf(s0, w2.x, s1 * w2.y);
#pragma unroll
        for (int off = 16; off; off >>= 1)
            v += __shfl_down_sync(0xffffffffu, v, off);
        q[a] = v;                          // valid in lane 0
    }

    if (lane == 0) {
        float bias = b2[0];
#pragma unroll
        for (int a = 0; a < 2; a++) {
            int i = base + a0 + a;
            if (i >= n) break;
            float qi = q[a] + bias;
            d_qraw[i] = qi;
            int g = batch[i];
            atomicAdd(&d_gsum[g * NSLOT + (i & (NSLOT - 1))], qi);
            // sorted-batch segment boundaries
            if (i == 0     || batch[i - 1] != g) d_gstart[g] = i;
            if (i == n - 1 || batch[i + 1] != g) d_gend[g]   = i + 1;
        }
    }
}

// ---------------------------------------------------------------------------
// K2: pack {pos, centered q} into float4. Per-graph mean reduced from the
//     slotted sums into SMEM at block start (no separate mean kernel).
// ---------------------------------------------------------------------------
__global__ void pack_kernel(const float* __restrict__ pos,
                            const int* __restrict__ batch, int n, int nb) {
    __shared__ float smean[MAXB];
    int t = threadIdx.x;                   // 256 threads
    if (t < MAXB) smean[t] = 0.0f;
    __syncthreads();
    for (int s = t; s < nb * NSLOT; s += 256)
        atomicAdd(&smean[s / NSLOT], d_gsum[s]);
    __syncthreads();

    int i = blockIdx.x * 256 + t;
    if (i < n) {
        int g = batch[i];
        float cnt  = (float)max(1, d_gend[g] - d_gstart[g]);
        float mean = smean[g] / cnt;
        float qc = d_qraw[i] - mean;
        d_qpos[i] = make_float4(pos[3 * i], pos[3 * i + 1], pos[3 * i + 2], qc);
    }
}

// ---------------------------------------------------------------------------
// K3: screened Coulomb pair sum. One warp per atom i; lanes stride over the
//     atom's contiguous graph range [gs, ge), unrolled x4 for 4 independent
//     MUFU chains (raw RSQ/EX2: 2 MUFU per pair). Self-term included in the
//     loop and subtracted with the IDENTICAL sequence so error cancels.
//     Tail duty: block 0 re-zeroes d_gsum for the next graph replay.
// ---------------------------------------------------------------------------
__device__ __forceinline__ float pair_term(float4 pj, float4 pi,
                                           float soft2, float nscr_log2e,
                                           float& k_out) {
    float dx = pj.x - pi.x;
    float dy = pj.y - pi.y;
    float dz = pj.z - pi.z;
    float r2 = fmaf(dx, dx, fmaf(dy, dy, fmaf(dz, dz, soft2)));
    float rinv = fast_rsqrt(r2);
    float r = r2 * rinv;
    k_out = fast_ex2(nscr_log2e * r) * rinv;
    return pj.w;
}

__global__ void pair_kernel(const int* __restrict__ batch,
                            const float* __restrict__ scr_p,
                            const float* __restrict__ soft_p,
                            float* __restrict__ out, int n) {
    // reset slotted accumulators for the next replay (values already consumed)
    if (blockIdx.x == 0) {
#pragma unroll
        for (int s = threadIdx.x; s < MAXB * NSLOT; s += 256)
            d_gsum[s] = 0.0f;
    }

    int i    = (blockIdx.x * blockDim.x + threadIdx.x) >> 5;
    int lane = threadIdx.x & 31;
    if (i >= n) return;

    const float4* __restrict__ qp = d_qpos;

    float scr   = *scr_p;
    float soft  = *soft_p;
    float soft2 = soft * soft;
    const float nscr_log2e = -scr * LOG2E;

    int g  = batch[i];
    int gs = d_gstart[g];
    int ge = d_gend[g];

    float4 pi = qp[i];
    float acc = 0.0f;

    int jlast = ge - 1;
    for (int j0 = gs + lane; j0 < ge; j0 += 128) {
        int j1 = j0 + 32, j2 = j0 + 64, j3 = j0 + 96;
        float4 p0 = qp[min(j0, jlast)];
        float4 p1 = qp[min(j1, jlast)];
        float4 p2 = qp[min(j2, jlast)];
        float4 p3 = qp[min(j3, jlast)];
        float k0, k1, k2, k3;
        float q0 = pair_term(p0, pi, soft2, nscr_log2e, k0);
        float q1 = pair_term(p1, pi, soft2, nscr_log2e, k1);
        float q2 = pair_term(p2, pi, soft2, nscr_log2e, k2);
        float q3 = pair_term(p3, pi, soft2, nscr_log2e, k3);
        acc = fmaf(q0, k0, acc);                 // j0 < ge by loop condition
        if (j1 < ge) acc = fmaf(q1, k1, acc);
        if (j2 < ge) acc = fmaf(q2, k2, acc);
        if (j3 < ge) acc = fmaf(q3, k3, acc);
    }

    // subtract self-term computed with the same intrinsic sequence
    if (lane == 0) {
        float ks;
        float qs = pair_term(pi, pi, soft2, nscr_log2e, ks);
        acc -= qs * ks;
    }

#pragma unroll
    for (int off = 16; off; off >>= 1)
        acc += __shfl_down_sync(0xffffffffu, acc, off);

    if (lane == 0) out[i] = 0.5f * pi.w * acc;
}

// ---------------------------------------------------------------------------
// launch
// inputs: 0:x 1:pos 2:cell 3:W1 4:b1 5:W2 6:b2 7:screening 8:softening 9:batch
// ---------------------------------------------------------------------------
extern "C" void kernel_launch(void* const* d_in, const int* in_sizes, int n_in,
                              void* d_out, int out_size) {
    const float* x     = (const float*)d_in[0];
    const float* pos   = (const float*)d_in[1];
    const float* W1    = (const float*)d_in[3];
    const float* b1    = (const float*)d_in[4];
    const float* W2    = (const float*)d_in[5];
    const float* b2    = (const float*)d_in[6];
    const float* scr   = (const float*)d_in[7];
    const float* soft  = (const float*)d_in[8];
    const int*   batch = (const int*)d_in[9];
    float* out = (float*)d_out;

    int n  = in_sizes[9];          // N atoms
    int nb = in_sizes[2] / 9;      // B graphs (cell is [B,3,3])
    if (nb > MAXB) nb = MAXB;

    mlp_kernel<<<(n + ATOMS_PER_BLK - 1) / ATOMS_PER_BLK, 256>>>(x, W1, b1, W2, b2, batch, n);
    pack_kernel<<<(n + 255) / 256, 256>>>(pos, batch, n, nb);
    int threads = 256;
    int blocks  = (n * 32 + threads - 1) / threads;
    pair_kernel<<<blocks, threads>>>(batch, scr, soft, out, n);
}

// round 7
// speedup vs baseline: 1.5384x; 1.5384x over previous
#include <cuda_runtime.h>

// Problem constants (LatentCoulombLongRange: N=8192, F=128, H=64, B=8)
#define MAXN 8192
#define FDIM 128
#define HDIM 64
#define MAXB 64
#define NSLOT 32          // charge-sum slots per graph (atomic de-serialization)

// Scratch (allocation-free rule: __device__ globals; zero-initialized at load)
__device__ float  d_qraw[MAXN];
__device__ float4 d_qpos[MAXN];            // {x, y, z, centered q}
__device__ int    d_gstart[MAXB];
__device__ int    d_gend[MAXB];
__device__ float  d_gsum[MAXB * NSLOT];    // slotted per-graph q sums; re-zeroed by pair_kernel

// ---- raw single-MUFU intrinsics (avoid non-fast-math slow paths) ----------
__device__ __forceinline__ float fast_rsqrt(float x) {
    float r; asm("rsqrt.approx.ftz.f32 %0, %1;" : "=f"(r) : "f"(x)); return r;
}
__device__ __forceinline__ float fast_ex2(float x) {
    float r; asm("ex2.approx.ftz.f32 %0, %1;" : "=f"(r) : "f"(x)); return r;
}
__device__ __forceinline__ float fast_rcp(float x) {
    float r; asm("rcp.approx.ftz.f32 %0, %1;" : "=f"(r) : "f"(x)); return r;
}

#define LOG2E 1.44269504088896f

__device__ __forceinline__ float f4c(float4 v, int s) {
    return (s == 0) ? v.x : (s == 1) ? v.y : (s == 2) ? v.z : v.w;
}

// ---------------------------------------------------------------------------
// K1: charge-head MLP  q_raw[i] = (silu(x W1 + b1) W2 + b2)
//     2-D decomposition: block = 512 threads / 16 warps, 16 atoms.
//     Warp (g = w&3, q = w>>2) computes atoms g*4..g*4+3 over f in
//     [q*32, q*32+32). 4 atoms/warp amortizes the w-crossbar; 4-way f-split
//     keeps 8192 warps in flight (occ ~80%) to hide LDS latency.
//     Quarter-partials combined through SMEM; warps 0-3 finalize.
// ---------------------------------------------------------------------------
__global__ __launch_bounds__(512, 3)
void mlp_kernel(const float* __restrict__ x,
                const float* __restrict__ W1,
                const float* __restrict__ b1,
                const float* __restrict__ W2,
                const float* __restrict__ b2,
                const int* __restrict__ batch,
                int n) {
    int w    = threadIdx.x >> 5;           // 0..15
    int lane = threadIdx.x & 31;
    int base = blockIdx.x * 16;

    __shared__ float  sw[FDIM * HDIM];     // 32 KB
    __shared__ float  sx[16][FDIM];        // 8 KB
    __shared__ float2 spart[16][32][4];    // 16 KB: [warp][lane][atom]

    // stage W1: 2048 float4 / 512 threads = 4 each (L2-hot after wave 1)
    {
        const float4* wv = (const float4*)W1;
        float4*       dv = (float4*)sw;
#pragma unroll
        for (int t = 0; t < 4; t++)
            dv[threadIdx.x + t * 512] = wv[threadIdx.x + t * 512];
    }
    // stage x rows: 512 float4, 1 per thread (guard last partial block)
    {
        const float4* xv = (const float4*)x;
        int idx = base * (FDIM / 4) + threadIdx.x;
        if (idx < n * (FDIM / 4))
            ((float4*)sx)[threadIdx.x] = xv[idx];
    }
    __syncthreads();

    int g = w & 3;                         // atom group
    int q = w >> 2;                        // f quarter
    int a0 = g * 4;
    int fbase = q * 32;

    float2 acc[4] = {{0.f,0.f},{0.f,0.f},{0.f,0.f},{0.f,0.f}};
    const float2* swv = (const float2*)sw; // [128][32] float2

#pragma unroll
    for (int f4 = 0; f4 < 32; f4 += 4) {
        int f = fbase + f4;
        float4 xa = *(const float4*)&sx[a0 + 0][f];
        float4 xb = *(const float4*)&sx[a0 + 1][f];
        float4 xc = *(const float4*)&sx[a0 + 2][f];
        float4 xd = *(const float4*)&sx[a0 + 3][f];
#pragma unroll
        for (int s = 0; s < 4; s++) {
            float2 wv = swv[(f + s) * 32 + lane];
            float x0 = f4c(xa, s), x1 = f4c(xb, s), x2 = f4c(xc, s), x3 = f4c(xd, s);
            acc[0].x = fmaf(x0, wv.x, acc[0].x);  acc[0].y = fmaf(x0, wv.y, acc[0].y);
            acc[1].x = fmaf(x1, wv.x, acc[1].x);  acc[1].y = fmaf(x1, wv.y, acc[1].y);
            acc[2].x = fmaf(x2, wv.x, acc[2].x);  acc[2].y = fmaf(x2, wv.y, acc[2].y);
            acc[3].x = fmaf(x3, wv.x, acc[3].x);  acc[3].y = fmaf(x3, wv.y, acc[3].y);
        }
    }

    // publish quarter-partials
#pragma unroll
    for (int a = 0; a < 4; a++) spart[w][lane][a] = acc[a];
    __syncthreads();

    // warps 0-3 finalize: warp w' owns atom group g = w'
    if (w < 4) {
        float2 bb = ((const float2*)b1)[lane];
        float2 w2 = ((const float2*)W2)[lane];
        float qv[4];
#pragma unroll
        for (int a = 0; a < 4; a++) {
            float2 t = spart[0 * 4 + w][lane][a];
#pragma unroll
            for (int qq = 1; qq < 4; qq++) {
                float2 p = spart[qq * 4 + w][lane][a];
                t.x += p.x;  t.y += p.y;
            }
            t.x += bb.x;  t.y += bb.y;
            float s0 = t.x * fast_rcp(1.0f + fast_ex2(-LOG2E * t.x));
            float s1 = t.y * fast_rcp(1.0f + fast_ex2(-LOG2E * t.y));
            float v = fmaf(s0, w2.x, s1 * w2.y);
#pragma unroll
            for (int off = 16; off; off >>= 1)
                v += __shfl_down_sync(0xffffffffu, v, off);
            qv[a] = v;                     // valid in lane 0
        }

        if (lane == 0) {
            float bias = b2[0];
#pragma unroll
            for (int a = 0; a < 4; a++) {
                int i = base + w * 4 + a;
                if (i >= n) break;
                float qi = qv[a] + bias;
                d_qraw[i] = qi;
                int gg = batch[i];
                atomicAdd(&d_gsum[gg * NSLOT + (i & (NSLOT - 1))], qi);
                // sorted-batch segment boundaries
                if (i == 0     || batch[i - 1] != gg) d_gstart[gg] = i;
                if (i == n - 1 || batch[i + 1] != gg) d_gend[gg]   = i + 1;
            }
        }
    }
}

// ---------------------------------------------------------------------------
// K2: pack {pos, centered q} into float4. Per-graph mean reduced from the
//     slotted sums into SMEM at block start (no separate mean kernel).
// ---------------------------------------------------------------------------
__global__ void pack_kernel(const float* __restrict__ pos,
                            const int* __restrict__ batch, int n, int nb) {
    __shared__ float smean[MAXB];
    int t = threadIdx.x;                   // 256 threads
    if (t < MAXB) smean[t] = 0.0f;
    __syncthreads();
    for (int s = t; s < nb * NSLOT; s += 256)
        atomicAdd(&smean[s / NSLOT], d_gsum[s]);
    __syncthreads();

    int i = blockIdx.x * 256 + t;
    if (i < n) {
        int g = batch[i];
        float cnt  = (float)max(1, d_gend[g] - d_gstart[g]);
        float mean = smean[g] / cnt;
        float qc = d_qraw[i] - mean;
        d_qpos[i] = make_float4(pos[3 * i], pos[3 * i + 1], pos[3 * i + 2], qc);
    }
}

// ---------------------------------------------------------------------------
// K3: screened Coulomb pair sum. One warp per atom i; lanes stride over the
//     atom's contiguous graph range [gs, ge), unrolled x4 for 4 independent
//     MUFU chains (raw RSQ/EX2: 2 MUFU per pair). Self-term included in the
//     loop and subtracted with the IDENTICAL sequence so error cancels.
//     Tail duty: block 0 re-zeroes d_gsum for the next graph replay.
// ---------------------------------------------------------------------------
__device__ __forceinline__ float pair_term(float4 pj, float4 pi,
                                           float soft2, float nscr_log2e,
                                           float& k_out) {
    float dx = pj.x - pi.x;
    float dy = pj.y - pi.y;
    float dz = pj.z - pi.z;
    float r2 = fmaf(dx, dx, fmaf(dy, dy, fmaf(dz, dz, soft2)));
    float rinv = fast_rsqrt(r2);
    float r = r2 * rinv;
    k_out = fast_ex2(nscr_log2e * r) * rinv;
    return pj.w;
}

__global__ void pair_kernel(const int* __restrict__ batch,
                            const float* __restrict__ scr_p,
                            const float* __restrict__ soft_p,
                            float* __restrict__ out, int n) {
    // reset slotted accumulators for the next replay (values already consumed)
    if (blockIdx.x == 0) {
#pragma unroll
        for (int s = threadIdx.x; s < MAXB * NSLOT; s += 256)
            d_gsum[s] = 0.0f;
    }

    int i    = (blockIdx.x * blockDim.x + threadIdx.x) >> 5;
    int lane = threadIdx.x & 31;
    if (i >= n) return;

    const float4* __restrict__ qp = d_qpos;

    float scr   = *scr_p;
    float soft  = *soft_p;
    float soft2 = soft * soft;
    const float nscr_log2e = -scr * LOG2E;

    int g  = batch[i];
    int gs = d_gstart[g];
    int ge = d_gend[g];

    float4 pi = qp[i];
    float acc = 0.0f;

    int jlast = ge - 1;
    for (int j0 = gs + lane; j0 < ge; j0 += 128) {
        int j1 = j0 + 32, j2 = j0 + 64, j3 = j0 + 96;
        float4 p0 = qp[min(j0, jlast)];
        float4 p1 = qp[min(j1, jlast)];
        float4 p2 = qp[min(j2, jlast)];
        float4 p3 = qp[min(j3, jlast)];
        float k0, k1, k2, k3;
        float q0 = pair_term(p0, pi, soft2, nscr_log2e, k0);
        float q1 = pair_term(p1, pi, soft2, nscr_log2e, k1);
        float q2 = pair_term(p2, pi, soft2, nscr_log2e, k2);
        float q3 = pair_term(p3, pi, soft2, nscr_log2e, k3);
        acc = fmaf(q0, k0, acc);                 // j0 < ge by loop condition
        if (j1 < ge) acc = fmaf(q1, k1, acc);
        if (j2 < ge) acc = fmaf(q2, k2, acc);
        if (j3 < ge) acc = fmaf(q3, k3, acc);
    }

    // subtract self-term computed with the same intrinsic sequence
    if (lane == 0) {
        float ks;
        float qs = pair_term(pi, pi, soft2, nscr_log2e, ks);
        acc -= qs * ks;
    }

#pragma unroll
    for (int off = 16; off; off >>= 1)
        acc += __shfl_down_sync(0xffffffffu, acc, off);

    if (lane == 0) out[i] = 0.5f * pi.w * acc;
}

// ---------------------------------------------------------------------------
// launch
// inputs: 0:x 1:pos 2:cell 3:W1 4:b1 5:W2 6:b2 7:screening 8:softening 9:batch
// ---------------------------------------------------------------------------
extern "C" void kernel_launch(void* const* d_in, const int* in_sizes, int n_in,
                              void* d_out, int out_size) {
    const float* x     = (const float*)d_in[0];
    const float* pos   = (const float*)d_in[1];
    const float* W1    = (const float*)d_in[3];
    const float* b1    = (const float*)d_in[4];
    const float* W2    = (const float*)d_in[5];
    const float* b2    = (const float*)d_in[6];
    const float* scr   = (const float*)d_in[7];
    const float* soft  = (const float*)d_in[8];
    const int*   batch = (const int*)d_in[9];
    float* out = (float*)d_out;

    int n  = in_sizes[9];          // N atoms
    int nb = in_sizes[2] / 9;      // B graphs (cell is [B,3,3])
    if (nb > MAXB) nb = MAXB;

    mlp_kernel<<<(n + 15) / 16, 512>>>(x, W1, b1, W2, b2, batch, n);
    pack_kernel<<<(n + 255) / 256, 256>>>(pos, batch, n, nb);
    int threads = 256;
    int blocks  = (n * 32 + threads - 1) / threads;
    pair_kernel<<<blocks, threads>>>(batch, scr, soft, out, n);
}